// round 1
// baseline (speedup 1.0000x reference)
#include <cuda_runtime.h>
#include <cuda_bf16.h>
#include <mma.h>

using namespace nvcuda;

#define BATCH 32
#define SEQ   2048
#define BL    (BATCH*SEQ)   // 65536 rows
#define DD    768
#define HH    512
#define EPSF  1e-5f

// Scratch (static device allocations are allowed; runtime allocs are not)
__device__ float g_h[(size_t)BL * HH];   // 128 MB: post-GEMM1 activations
__device__ float g_sum[HH];
__device__ float g_sumsq[HH];
__device__ float g_mean[HH];
__device__ float g_rstdg[HH];            // rsqrt(var+eps)*gamma
__device__ float g_counts[BATCH];
__device__ float g_nvalid;
__device__ float g_pool[BATCH * HH];     // masked sum of relu(normed h)

// ---------------------------------------------------------------------------
// Zero accumulators (must happen every replay; graph-captured)
// ---------------------------------------------------------------------------
__global__ void k_init() {
    int i = blockIdx.x * blockDim.x + threadIdx.x;
    if (i < HH) { g_sum[i] = 0.f; g_sumsq[i] = 0.f; }
    if (i < BATCH * HH) g_pool[i] = 0.f;
    if (i == 0) g_nvalid = 0.f;
}

// ---------------------------------------------------------------------------
// Per-batch valid-token counts + total valid count
// ---------------------------------------------------------------------------
__global__ void k_counts(const int* __restrict__ mask) {
    __shared__ int sh[256];
    int b = blockIdx.x, t = threadIdx.x;
    int s = 0;
    for (int l = t; l < SEQ; l += 256) s += mask[b * SEQ + l];
    sh[t] = s;
    __syncthreads();
    for (int o = 128; o > 0; o >>= 1) {
        if (t < o) sh[t] += sh[t + o];
        __syncthreads();
    }
    if (t == 0) {
        g_counts[b] = fmaxf((float)sh[0], 1.f);
        atomicAdd(&g_nvalid, (float)sh[0]);
    }
}

// ---------------------------------------------------------------------------
// GEMM1: h = hidden[65536,768] @ W1[768,512]  (tf32 wmma, fp32 accumulate)
// b1 omitted: batch-norm mean-subtraction cancels any per-channel constant.
// ---------------------------------------------------------------------------
#define G1_BM 128
#define G1_BN 128
#define G1_BK 16

__global__ void __launch_bounds__(256) k_gemm1(const float* __restrict__ A,
                                               const float* __restrict__ B) {
    __shared__ float As[G1_BM][G1_BK + 4];
    __shared__ float Bs[G1_BK][G1_BN + 4];

    const int bm = blockIdx.y * G1_BM;
    const int bn = blockIdx.x * G1_BN;
    const int tid = threadIdx.x;
    const int warp = tid >> 5;
    const int wm = (warp >> 2) * 64;   // warp row offset within block tile
    const int wn = (warp & 3) * 32;    // warp col offset

    wmma::fragment<wmma::accumulator, 16, 16, 8, float> acc[4][2];
#pragma unroll
    for (int i = 0; i < 4; i++)
#pragma unroll
        for (int j = 0; j < 2; j++) wmma::fill_fragment(acc[i][j], 0.f);

    for (int k0 = 0; k0 < DD; k0 += G1_BK) {
        // load A tile 128x16 (float4 per 4 lanes per row)
#pragma unroll
        for (int i = tid; i < G1_BM * (G1_BK / 4); i += 256) {
            int r = i >> 2, c = (i & 3) * 4;
            float4 v = *(const float4*)(A + (size_t)(bm + r) * DD + k0 + c);
            As[r][c + 0] = wmma::__float_to_tf32(v.x);
            As[r][c + 1] = wmma::__float_to_tf32(v.y);
            As[r][c + 2] = wmma::__float_to_tf32(v.z);
            As[r][c + 3] = wmma::__float_to_tf32(v.w);
        }
        // load B tile 16x128 (fully coalesced)
#pragma unroll
        for (int i = tid; i < G1_BK * (G1_BN / 4); i += 256) {
            int r = i >> 5, c = (i & 31) * 4;
            float4 v = *(const float4*)(B + (size_t)(k0 + r) * HH + bn + c);
            Bs[r][c + 0] = wmma::__float_to_tf32(v.x);
            Bs[r][c + 1] = wmma::__float_to_tf32(v.y);
            Bs[r][c + 2] = wmma::__float_to_tf32(v.z);
            Bs[r][c + 3] = wmma::__float_to_tf32(v.w);
        }
        __syncthreads();

#pragma unroll
        for (int kk = 0; kk < G1_BK; kk += 8) {
            wmma::fragment<wmma::matrix_a, 16, 16, 8, wmma::precision::tf32, wmma::row_major> fa[4];
            wmma::fragment<wmma::matrix_b, 16, 16, 8, wmma::precision::tf32, wmma::row_major> fb[2];
#pragma unroll
            for (int i = 0; i < 4; i++)
                wmma::load_matrix_sync(fa[i], &As[wm + i * 16][kk], G1_BK + 4);
#pragma unroll
            for (int j = 0; j < 2; j++)
                wmma::load_matrix_sync(fb[j], &Bs[kk][wn + j * 16], G1_BN + 4);
#pragma unroll
            for (int i = 0; i < 4; i++)
#pragma unroll
                for (int j = 0; j < 2; j++)
                    wmma::mma_sync(acc[i][j], fa[i], fb[j], acc[i][j]);
        }
        __syncthreads();
    }

#pragma unroll
    for (int i = 0; i < 4; i++)
#pragma unroll
        for (int j = 0; j < 2; j++)
            wmma::store_matrix_sync(
                g_h + (size_t)(bm + wm + i * 16) * HH + bn + wn + j * 16,
                acc[i][j], HH, wmma::mem_row_major);
}

// ---------------------------------------------------------------------------
// Masked per-channel sum / sum-of-squares over all 65536 rows
// ---------------------------------------------------------------------------
__global__ void k_stats(const int* __restrict__ mask) {
    int c = blockIdx.x * 128 + threadIdx.x;
    int r0 = blockIdx.y * 256;
    float s = 0.f, q = 0.f;
    for (int r = r0; r < r0 + 256; r++) {
        if (mask[r]) {
            float v = g_h[(size_t)r * HH + c];
            s += v;
            q += v * v;
        }
    }
    atomicAdd(&g_sum[c], s);
    atomicAdd(&g_sumsq[c], q);
}

__global__ void k_finalize(const float* __restrict__ gamma) {
    int c = threadIdx.x;
    float n = fmaxf(g_nvalid, 1.f);
    float mean = g_sum[c] / n;
    float var = g_sumsq[c] / n - mean * mean;
    g_mean[c] = mean;
    g_rstdg[c] = rsqrtf(fmaxf(var, 0.f) + EPSF) * gamma[c];
}

// ---------------------------------------------------------------------------
// Normalize + ReLU + masked pool (sum over valid tokens of each batch)
// ---------------------------------------------------------------------------
__global__ void k_pool(const int* __restrict__ mask, const float* __restrict__ beta) {
    int b = blockIdx.x, c = threadIdx.x;
    int l0 = blockIdx.y * 128;
    float mean = g_mean[c], rs = g_rstdg[c], be = beta[c];
    float s = 0.f;
    const size_t base = (size_t)(b * SEQ + l0) * HH;
    for (int l = 0; l < 128; l++) {
        if (mask[b * SEQ + l0 + l]) {
            float v = g_h[base + (size_t)l * HH + c];
            v = (v - mean) * rs + be;
            s += fmaxf(v, 0.f);
        }
    }
    atomicAdd(&g_pool[b * HH + c], s);
}

// ---------------------------------------------------------------------------
// Tiny GEMM2 on pooled features: out[b,:] = (pool[b,:]/counts[b]) @ W2 + b2
// ---------------------------------------------------------------------------
__global__ void k_gemm2(const float* __restrict__ W2, const float* __restrict__ b2,
                        float* __restrict__ out) {
    __shared__ float ph[HH];
    int b = blockIdx.x, k = threadIdx.x;
    ph[k] = g_pool[b * HH + k] / g_counts[b];
    __syncthreads();
    float acc = b2[k];
#pragma unroll 8
    for (int c = 0; c < HH; c++) acc += ph[c] * W2[c * HH + k];
    out[b * HH + k] = acc;
}

// ---------------------------------------------------------------------------
extern "C" void kernel_launch(void* const* d_in, const int* in_sizes, int n_in,
                              void* d_out, int out_size) {
    const float* hidden = (const float*)d_in[0];
    const int*   mask   = (const int*)d_in[1];
    const float* W1     = (const float*)d_in[2];
    // d_in[3] = b1: mathematically cancelled by batch-norm mean subtraction
    const float* gamma  = (const float*)d_in[4];
    const float* beta   = (const float*)d_in[5];
    const float* W2     = (const float*)d_in[6];
    const float* b2     = (const float*)d_in[7];
    float* out = (float*)d_out;

    k_init<<<64, 256>>>();
    k_counts<<<BATCH, 256>>>(mask);
    k_gemm1<<<dim3(HH / G1_BN, BL / G1_BM), 256>>>(hidden, W1);
    k_stats<<<dim3(HH / 128, BL / 256), 128>>>(mask);
    k_finalize<<<1, HH>>>(gamma);
    k_pool<<<dim3(BATCH, SEQ / 128), 512>>>(mask, beta);
    k_gemm2<<<BATCH, HH>>>(W2, b2, out);
}